// round 5
// baseline (speedup 1.0000x reference)
#include <cuda_runtime.h>
#include <cstdint>
#include <float.h>
#include <math.h>

#define NB 16384
#define NJ 16384
#define NKF 64
#define NDIM 128
#define N_ELEM (NB * NDIM)
#define N_STAT_BLOCKS 2048
#define JSPLIT 16
#define JCHUNK (NJ / JSPLIT)

typedef unsigned long long ull;

// Scratch (device globals; no allocation allowed)
__device__ float g_zf2T[NKF * NB];     // 2*zf folded, [kf][b]
__device__ float g_zf2R[NB * NKF];     // 2*zf folded, row-major [b][kf]
__device__ float g_znorm[NB];
__device__ float g_ef2T[NKF * NJ];     // folded e sums, [kf][j]
__device__ ull   g_k1[NB * JSPLIT];    // per (row, split) best key (score|j)
__device__ unsigned g_v2[NB * JSPLIT]; // second-smallest score (value only)
__device__ int   g_idx[NB];
__device__ int   g_fbn;
__device__ int   g_fb[NB];
__device__ float g_partials[N_STAT_BLOCKS * 6];
__device__ float g_colpart[128 * 128];
__device__ float g_colmax;

// ---------------------------------------------------------------------------
__device__ __forceinline__ uint32_t smem_u32(const void* p) {
    uint32_t r;
    asm("{ .reg .u64 t; cvta.to.shared.u64 t, %1; cvt.u32.u64 %0, t; }"
        : "=r"(r) : "l"(p));
    return r;
}
__device__ __forceinline__ void lds_v2u64(ull& x, ull& y, uint32_t addr) {
    asm volatile("ld.shared.v2.u64 {%0,%1}, [%2];" : "=l"(x), "=l"(y) : "r"(addr));
}
__device__ __forceinline__ void ffma2(ull& d, ull a, ull b) {
    asm("fma.rn.f32x2 %0, %1, %2, %0;" : "+l"(d) : "l"(a), "l"(b));
}
__device__ __forceinline__ void unpack2(float& lo, float& hi, ull v) {
    asm("mov.b64 {%0,%1}, %2;" : "=f"(lo), "=f"(hi) : "l"(v));
}

// Exact-chain fold map: kf(k) = (k>>6)*32 + (((k>>3)&7)<<2) + (k&3)
__device__ __forceinline__ int kf_of_k(int k) {
    return ((k >> 6) << 5) + (((k >> 3) & 7) << 2) + (k & 3);
}

// ---------------------------------------------------------------------------
// zf2T[kf][b], zf2R[b][kf] = fl(z[b,c,h,2w'] + z[b,c,h,2w'+1]);
// znorm[b] = 0.5*sum(zf2^2). Also resets fallback counter.
// ---------------------------------------------------------------------------
__global__ void prep_z_kernel(const float* __restrict__ z) {
    int b = blockIdx.x * 128 + threadIdx.x;
    if (b == 0) g_fbn = 0;
    const float* zr = z + (size_t)b * NDIM;
    float sum = 0.f;
#pragma unroll
    for (int kf = 0; kf < NKF; kf++) {
        int c = kf >> 2, h = (kf >> 1) & 1, wp = kf & 1;
        int base = c * 8 + h * 4 + wp * 2;
        float2 p = *reinterpret_cast<const float2*>(zr + base);
        float v = p.x + p.y;
        g_zf2T[kf * NB + b] = v;
        g_zf2R[b * NKF + kf] = v;
        sum = fmaf(v, v, sum);
    }
    g_znorm[b] = 0.5f * sum;
}

// ---------------------------------------------------------------------------
// ef2T[kf][j] = fl(e[j][ka] + e[j][ka+4]),  ka = c*8 + h*2 + wp for
// kf = c*4 + h*2 + wp  (matches kf_of_k inverse).
// ---------------------------------------------------------------------------
__global__ void fold_e_kernel(const float* __restrict__ e) {
    int j = blockIdx.x * 128 + threadIdx.x;
    const float* er = e + (size_t)j * NDIM;
#pragma unroll
    for (int kf = 0; kf < NKF; kf++) {
        int ks = kf >> 5, q = kf & 31, g = q >> 2, r = q & 3;
        int ka = ks * 64 + g * 8 + r;
        g_ef2T[kf * NJ + j] = er[ka] + er[ka + 4];
    }
}

// ---------------------------------------------------------------------------
__global__ void colmax1_kernel(const float* __restrict__ e) {
    int t = threadIdx.x;
    int r0 = blockIdx.x * 128;
    float s = 0.f;
    for (int r = 0; r < 128; r++)
        s += fabsf(e[(size_t)(r0 + r) * NDIM + t]);
    g_colpart[blockIdx.x * 128 + t] = s;
}
__global__ void colmax2_kernel() {
    __shared__ float sm[128];
    int t = threadIdx.x;
    float s = 0.f;
    for (int bi = 0; bi < 128; bi++) s += g_colpart[bi * 128 + t];
    sm[t] = s;
    __syncthreads();
    for (int off = 64; off > 0; off >>= 1) {
        if (t < off) sm[t] = fmaxf(sm[t], sm[t + off]);
        __syncthreads();
    }
    if (t == 0) g_colmax = sm[0];
}

// ---------------------------------------------------------------------------
// Pass 1: folded K=64 FFMA2 GEMM (R3-proven inner loop: zf duplicated in
// smem, 6 LDS.128 + 32 FFMA2 per kk). Per (row, split) emit best key + the
// second-smallest score VALUE. Minimal register tracking: 3 regs/row.
// Block: 64 rows x 1024 codes, 128 threads, 8 rows x 8 cols/thread.
// ---------------------------------------------------------------------------
__global__ void __launch_bounds__(128, 3) pass1_kernel() {
    __shared__ float zf_dup[NKF][128];   // 32 KB: [kf][2m]=[kf][2m+1]
    __shared__ float e_s[32][128];       // 16 KB: 32-kf chunk

    int tid = threadIdx.x;
    int tm8 = (tid >> 4) * 8;
    int tn8 = (tid & 15) * 8;
    int row0 = (blockIdx.x & 255) * 64;
    int jsplit = blockIdx.x >> 8;
    int jbase = jsplit * JCHUNK;

    // stage duplicated zf tile
#pragma unroll
    for (int it = 0; it < 8; it++) {
        int f4 = it * 128 + tid;
        int kf = f4 >> 4, m4 = f4 & 15;
        float4 v = *reinterpret_cast<const float4*>(&g_zf2T[kf * NB + row0 + m4 * 4]);
        *reinterpret_cast<float4*>(&zf_dup[kf][m4 * 8]) =
            make_float4(v.x, v.x, v.y, v.y);
        *reinterpret_cast<float4*>(&zf_dup[kf][m4 * 8 + 4]) =
            make_float4(v.z, v.z, v.w, v.w);
    }
    float zn[8];
#pragma unroll
    for (int r = 0; r < 8; r++) zn[r] = g_znorm[row0 + tm8 + r];

    ull k1[8];
    unsigned v2[8];
#pragma unroll
    for (int r = 0; r < 8; r++) { k1[r] = ~0ULL; v2[r] = 0xFFFFFFFFu; }

    uint32_t sa = smem_u32(zf_dup) + tm8 * 8;
    uint32_t sb = smem_u32(e_s) + tn8 * 4;

    for (int t = 0; t < JCHUNK / 128; t++) {
        int j0 = jbase + t * 128;
        ull acc[8][4];
#pragma unroll
        for (int r = 0; r < 8; r++)
#pragma unroll
            for (int c = 0; c < 4; c++) acc[r][c] = 0ULL;

#pragma unroll
        for (int ks = 0; ks < 2; ks++) {
            __syncthreads();
#pragma unroll
            for (int it = 0; it < 8; it++) {
                int f4 = it * 128 + tid;
                int kk = f4 >> 5, n4 = f4 & 31;
                *reinterpret_cast<float4*>(&e_s[kk][n4 * 4]) =
                    *reinterpret_cast<const float4*>(
                        &g_ef2T[(size_t)(ks * 32 + kk) * NJ + j0 + n4 * 4]);
            }
            __syncthreads();

            uint32_t sa_ks = sa + ks * 32 * 512;
#pragma unroll
            for (int kk = 0; kk < 32; kk++) {
                ull a0, a1, a2, a3, a4, a5, a6, a7, b0, b1, b2, b3;
                lds_v2u64(a0, a1, sa_ks + kk * 512);
                lds_v2u64(a2, a3, sa_ks + kk * 512 + 16);
                lds_v2u64(a4, a5, sa_ks + kk * 512 + 32);
                lds_v2u64(a6, a7, sa_ks + kk * 512 + 48);
                lds_v2u64(b0, b1, sb + kk * 512);
                lds_v2u64(b2, b3, sb + kk * 512 + 16);
                ull av[8] = {a0, a1, a2, a3, a4, a5, a6, a7};
                ull bv[4] = {b0, b1, b2, b3};
#pragma unroll
                for (int r = 0; r < 8; r++)
#pragma unroll
                    for (int cc = 0; cc < 4; cc++)
                        ffma2(acc[r][cc], av[r], bv[cc]);
            }
        }

        // epilogue: s = fl(zn - dot) > 0; raw bits are sortable.
        int jt = j0 + tn8;
#pragma unroll
        for (int cp = 0; cp < 4; cp++) {
#pragma unroll
            for (int r = 0; r < 8; r++) {
                float lo, hi;
                unpack2(lo, hi, acc[r][cp]);
                unsigned u0 = __float_as_uint(zn[r] - lo);
                if (u0 < v2[r]) {
                    ull key = ((ull)u0 << 32) | (unsigned)(jt + 2 * cp);
                    if (key < k1[r]) { v2[r] = (unsigned)(k1[r] >> 32); k1[r] = key; }
                    else v2[r] = u0;
                }
                unsigned u1 = __float_as_uint(zn[r] - hi);
                if (u1 < v2[r]) {
                    ull key = ((ull)u1 << 32) | (unsigned)(jt + 2 * cp + 1);
                    if (key < k1[r]) { v2[r] = (unsigned)(k1[r] >> 32); k1[r] = key; }
                    else v2[r] = u1;
                }
            }
        }
    }

    // block merge: 16 (k1,v2) per row -> block best key + 2nd-smallest value
    __syncthreads();
    char* mbuf = reinterpret_cast<char*>(&e_s[0][0]);
    ull* K1 = reinterpret_cast<ull*>(mbuf);                     // [64][16] 8KB
    unsigned* V2 = reinterpret_cast<unsigned*>(mbuf + 8192);    // [64][16] 4KB
    int tn = tid & 15;
#pragma unroll
    for (int r = 0; r < 8; r++) {
        K1[(tm8 + r) * 16 + tn] = k1[r];
        V2[(tm8 + r) * 16 + tn] = v2[r];
    }
    __syncthreads();
    if (tid < 64) {
        ull bk1 = ~0ULL;
        unsigned bv2 = 0xFFFFFFFFu;
        for (int q = 0; q < 16; q++) {
            ull K = K1[tid * 16 + q];
            if (K < bk1) {
                unsigned s = (unsigned)(bk1 >> 32);
                if (s < bv2) bv2 = s;
                bk1 = K;
            } else {
                unsigned s = (unsigned)(K >> 32);
                if (s < bv2) bv2 = s;
            }
            unsigned v = V2[tid * 16 + q];
            if (v < bv2) bv2 = v;
        }
        int o = (row0 + tid) * JSPLIT + jsplit;
        g_k1[o] = bk1;
        g_v2[o] = bv2;
    }
}

// ---------------------------------------------------------------------------
// Merge per row: window over split bests; exact re-rank of candidate j's
// (proven R3 chain); rows where any split's 2nd value enters the window get
// a full exact fallback scan.
// ---------------------------------------------------------------------------
__global__ void merge_exact_kernel(const float* __restrict__ e) {
    int b = blockIdx.x * 256 + threadIdx.x;
    float zn = g_znorm[b];
    float ulp = ldexpf(1.0f, ilogbf(fmaxf(zn, 1e-30f)) - 23);
    float W = 2.0f * ulp + 1e-6f;

    ull k1v[JSPLIT];
    unsigned v2v[JSPLIT];
    unsigned mu = 0xFFFFFFFFu;
#pragma unroll
    for (int s = 0; s < JSPLIT; s++) {
        k1v[s] = g_k1[b * JSPLIT + s];
        v2v[s] = g_v2[b * JSPLIT + s];
        unsigned sc = (unsigned)(k1v[s] >> 32);
        if (sc < mu) mu = sc;
    }
    float thr = __uint_as_float(mu) + W;
    unsigned thr_u = __float_as_uint(thr);

    int cj[JSPLIT];
    int nc = 0;
    bool flag = false;
#pragma unroll
    for (int s = 0; s < JSPLIT; s++) {
        if ((unsigned)(k1v[s] >> 32) <= thr_u) cj[nc++] = (int)(unsigned)k1v[s];
        if (v2v[s] <= thr_u) flag = true;
    }
    if (flag) {
        int p = atomicAdd(&g_fbn, 1);
        g_fb[p] = b;
        return;
    }
    // exact chain (bitwise reference order) on candidates
    float zfr[NKF];
    const float4* zr4 = reinterpret_cast<const float4*>(&g_zf2R[b * NKF]);
#pragma unroll
    for (int i = 0; i < 16; i++) {
        float4 v = zr4[i];
        zfr[i * 4] = v.x; zfr[i * 4 + 1] = v.y;
        zfr[i * 4 + 2] = v.z; zfr[i * 4 + 3] = v.w;
    }
    float bestd = FLT_MAX;
    int bestj = 0x7FFFFFFF;
    for (int i = 0; i < nc; i++) {
        int j = cj[i];
        const float* er = e + (size_t)j * NDIM;
        float acc = 0.f;
#pragma unroll
        for (int k = 0; k < NDIM; k++)
            acc = fmaf(zfr[kf_of_k(k)], er[k], acc);
        float d = zn - acc;
        if (d < bestd || (d == bestd && j < bestj)) { bestd = d; bestj = j; }
    }
    g_idx[b] = bestj;
}

// ---------------------------------------------------------------------------
// Fallback: full exact scan for flagged rows (expected ~0.7% of rows).
// ---------------------------------------------------------------------------
__global__ void fallback_kernel(const float* __restrict__ e) {
    __shared__ float zfs[NKF];
    __shared__ ull slot;
    int n = g_fbn;
    for (int fi = blockIdx.x; fi < n; fi += gridDim.x) {
        int b = g_fb[fi];
        if (threadIdx.x < NKF) zfs[threadIdx.x] = g_zf2R[b * NKF + threadIdx.x];
        if (threadIdx.x == 0) slot = ~0ULL;
        __syncthreads();
        float zn = g_znorm[b];
        ull lb = ~0ULL;
        for (int j = threadIdx.x; j < NJ; j += 256) {
            const float* er = e + (size_t)j * NDIM;
            float acc = 0.f;
#pragma unroll
            for (int k = 0; k < NDIM; k++)
                acc = fmaf(zfs[kf_of_k(k)], er[k], acc);
            float d = zn - acc;
            ull key = ((ull)__float_as_uint(d) << 32) | (unsigned)j;
            if (key < lb) lb = key;
        }
        atomicMin(&slot, lb);
        __syncthreads();
        if (threadIdx.x == 0) g_idx[b] = (int)(slot & 0xFFFFFFFFu);
        __syncthreads();
    }
}

// ---------------------------------------------------------------------------
// Gather z_q, write transposed output replicating z + fl(z_q - z), stats.
// ---------------------------------------------------------------------------
__global__ void gather_stats_kernel(const float* __restrict__ z,
                                    const float* __restrict__ e,
                                    float* __restrict__ outF, int out_size) {
    int t = blockIdx.x * 256 + threadIdx.x;
    int g0 = t * 4;
    int b = g0 >> 7;
    int i0 = g0 & 127;
    int j = g_idx[b];
    float4 zv = *reinterpret_cast<const float4*>(z + g0);
    float4 qv = *reinterpret_cast<const float4*>(e + (size_t)j * NDIM + i0);

    float q[4] = {qv.x, qv.y, qv.z, qv.w};
    float zz[4] = {zv.x, zv.y, zv.z, zv.w};
    float d[4], o[4];
#pragma unroll
    for (int u = 0; u < 4; u++) {
        d[u] = __fsub_rn(q[u], zz[u]);
        o[u] = __fadd_rn(zz[u], d[u]);
    }
    int c = i0 >> 3, h = (i0 >> 2) & 1;
    int ob = b * 128 + c * 2 + h;
    outF[ob]      = o[0];
    outF[ob + 32] = o[1];
    outF[ob + 64] = o[2];
    outF[ob + 96] = o[3];
    if (i0 == 0 && out_size >= N_ELEM + 1 + NB)
        outF[N_ELEM + 1 + b] = (float)j;

    float sd2 = 0.f, s1 = 0.f, s2 = 0.f, sxx = 0.f, syy = 0.f, sxy = 0.f;
#pragma unroll
    for (int u = 0; u < 4; u++) {
        sd2 = fmaf(d[u], d[u], sd2);
        s1 += q[u];
        s2 += zz[u];
        sxx = fmaf(q[u], q[u], sxx);
        syy = fmaf(zz[u], zz[u], syy);
        sxy = fmaf(q[u], zz[u], sxy);
    }
#pragma unroll
    for (int off = 16; off; off >>= 1) {
        sd2 += __shfl_down_sync(0xFFFFFFFFu, sd2, off);
        s1  += __shfl_down_sync(0xFFFFFFFFu, s1, off);
        s2  += __shfl_down_sync(0xFFFFFFFFu, s2, off);
        sxx += __shfl_down_sync(0xFFFFFFFFu, sxx, off);
        syy += __shfl_down_sync(0xFFFFFFFFu, syy, off);
        sxy += __shfl_down_sync(0xFFFFFFFFu, sxy, off);
    }
    __shared__ float sm[8][6];
    int wid = threadIdx.x >> 5, lane = threadIdx.x & 31;
    if (lane == 0) {
        sm[wid][0] = sd2; sm[wid][1] = s1; sm[wid][2] = s2;
        sm[wid][3] = sxx; sm[wid][4] = syy; sm[wid][5] = sxy;
    }
    __syncthreads();
    if (threadIdx.x < 6) {
        float a = 0.f;
#pragma unroll
        for (int w = 0; w < 8; w++) a += sm[w][threadIdx.x];
        g_partials[blockIdx.x * 6 + threadIdx.x] = a;
    }
}

// ---------------------------------------------------------------------------
__global__ void final_reduce_kernel(float* __restrict__ outF, int out_size) {
    __shared__ double smr[256];
    __shared__ double tot[6];
    double acc[6] = {0, 0, 0, 0, 0, 0};
    for (int p = threadIdx.x; p < N_STAT_BLOCKS; p += 256) {
#pragma unroll
        for (int s = 0; s < 6; s++) acc[s] += (double)g_partials[p * 6 + s];
    }
    for (int s = 0; s < 6; s++) {
        smr[threadIdx.x] = acc[s];
        __syncthreads();
        for (int off = 128; off > 0; off >>= 1) {
            if (threadIdx.x < off) smr[threadIdx.x] += smr[threadIdx.x + off];
            __syncthreads();
        }
        if (threadIdx.x == 0) tot[s] = smr[0];
        __syncthreads();
    }
    if (threadIdx.x == 0 && out_size >= N_ELEM + 1) {
        double N = (double)N_ELEM;
        double commit = 1.25 * tot[0] / N;
        double cov = tot[5] - tot[1] * tot[2] / N;
        double vx = tot[3] - tot[1] * tot[1] / N;
        double vy = tot[4] - tot[2] * tot[2] / N;
        double pearson = 0.5 + 0.5 * cov / (sqrt(vx) * sqrt(vy));
        double loss = commit + pearson + 0.01 * (double)g_colmax;
        outF[N_ELEM] = (float)loss;
    }
}

// ---------------------------------------------------------------------------
extern "C" void kernel_launch(void* const* d_in, const int* in_sizes, int n_in,
                              void* d_out, int out_size) {
    const float* z = (const float*)d_in[0];
    const float* e = (const float*)d_in[1];
    float* out = (float*)d_out;

    prep_z_kernel<<<NB / 128, 128>>>(z);
    fold_e_kernel<<<NJ / 128, 128>>>(e);
    colmax1_kernel<<<128, 128>>>(e);
    colmax2_kernel<<<1, 128>>>();
    pass1_kernel<<<256 * JSPLIT, 128>>>();
    merge_exact_kernel<<<NB / 256, 256>>>(e);
    fallback_kernel<<<32, 256>>>(e);
    gather_stats_kernel<<<N_ELEM / 1024, 256>>>(z, e, out, out_size);
    final_reduce_kernel<<<1, 256>>>(out, out_size);
}

// round 6
// speedup vs baseline: 3.2412x; 3.2412x over previous
#include <cuda_runtime.h>
#include <cstdint>
#include <float.h>
#include <math.h>

#define NB 16384
#define NJ 16384
#define NKF 64
#define NDIM 128
#define N_ELEM (NB * NDIM)
#define N_STAT_BLOCKS 2048
#define JSPLIT 16
#define JCHUNK (NJ / JSPLIT)

typedef unsigned long long ull;

// Scratch (device globals; no allocation allowed)
__device__ float g_zf2T[NKF * NB];     // 2*zf folded, [kf][b]
__device__ float g_zf2R[NB * NKF];     // 2*zf folded, row-major [b][kf]
__device__ float g_znorm[NB];
__device__ float g_ef2T[NKF * NJ];     // folded e sums, [kf][j]
__device__ ull   g_k1[NB * JSPLIT];    // per (row, split) best key (score|j)
__device__ ull   g_k2[NB * JSPLIT];    // per (row, split) 2nd key (score|j)
__device__ unsigned g_v3[NB * JSPLIT]; // guard value (3rd-smallest bound)
__device__ int   g_idx[NB];
__device__ int   g_fbn;
__device__ int   g_fb[NB];
__device__ float g_partials[N_STAT_BLOCKS * 6];
__device__ float g_colpart[128 * 128];
__device__ float g_colmax;

// ---------------------------------------------------------------------------
__device__ __forceinline__ uint32_t smem_u32(const void* p) {
    uint32_t r;
    asm("{ .reg .u64 t; cvta.to.shared.u64 t, %1; cvt.u32.u64 %0, t; }"
        : "=r"(r) : "l"(p));
    return r;
}
__device__ __forceinline__ void lds_v2u64(ull& x, ull& y, uint32_t addr) {
    asm volatile("ld.shared.v2.u64 {%0,%1}, [%2];" : "=l"(x), "=l"(y) : "r"(addr));
}
__device__ __forceinline__ void ffma2(ull& d, ull a, ull b) {
    asm("fma.rn.f32x2 %0, %1, %2, %0;" : "+l"(d) : "l"(a), "l"(b));
}
__device__ __forceinline__ void unpack2(float& lo, float& hi, ull v) {
    asm("mov.b64 {%0,%1}, %2;" : "=f"(lo), "=f"(hi) : "l"(v));
}

// Exact-chain fold map: kf(k) = (k>>6)*32 + (((k>>3)&7)<<2) + (k&3)
__device__ __forceinline__ int kf_of_k(int k) {
    return ((k >> 6) << 5) + (((k >> 3) & 7) << 2) + (k & 3);
}

// ---------------------------------------------------------------------------
__global__ void prep_z_kernel(const float* __restrict__ z) {
    int b = blockIdx.x * 128 + threadIdx.x;
    if (b == 0) g_fbn = 0;
    const float* zr = z + (size_t)b * NDIM;
    float sum = 0.f;
#pragma unroll
    for (int kf = 0; kf < NKF; kf++) {
        int c = kf >> 2, h = (kf >> 1) & 1, wp = kf & 1;
        int base = c * 8 + h * 4 + wp * 2;
        float2 p = *reinterpret_cast<const float2*>(zr + base);
        float v = p.x + p.y;
        g_zf2T[kf * NB + b] = v;
        g_zf2R[b * NKF + kf] = v;
        sum = fmaf(v, v, sum);
    }
    g_znorm[b] = 0.5f * sum;
}

// ---------------------------------------------------------------------------
__global__ void fold_e_kernel(const float* __restrict__ e) {
    int j = blockIdx.x * 128 + threadIdx.x;
    const float* er = e + (size_t)j * NDIM;
#pragma unroll
    for (int kf = 0; kf < NKF; kf++) {
        int ks = kf >> 5, q = kf & 31, g = q >> 2, r = q & 3;
        int ka = ks * 64 + g * 8 + r;
        g_ef2T[kf * NJ + j] = er[ka] + er[ka + 4];
    }
}

// ---------------------------------------------------------------------------
__global__ void colmax1_kernel(const float* __restrict__ e) {
    int t = threadIdx.x;
    int r0 = blockIdx.x * 128;
    float s = 0.f;
    for (int r = 0; r < 128; r++)
        s += fabsf(e[(size_t)(r0 + r) * NDIM + t]);
    g_colpart[blockIdx.x * 128 + t] = s;
}
__global__ void colmax2_kernel() {
    __shared__ float sm[128];
    int t = threadIdx.x;
    float s = 0.f;
    for (int bi = 0; bi < 128; bi++) s += g_colpart[bi * 128 + t];
    sm[t] = s;
    __syncthreads();
    for (int off = 64; off > 0; off >>= 1) {
        if (t < off) sm[t] = fmaxf(sm[t], sm[t + off]);
        __syncthreads();
    }
    if (t == 0) g_colmax = sm[0];
}

// ---------------------------------------------------------------------------
// Pass 1: folded K=64 FFMA2 GEMM. Conflict-free b loads: each thread's 8
// columns are j_local = {tn*4+u, 64+tn*4+u} so LDS.128 lane stride is 16B.
// Per-thread tracking: best key + 2nd-smallest value (3 regs/row).
// Block merge produces per (row, split): top-2 keys + guard value v3.
// ---------------------------------------------------------------------------
__global__ void __launch_bounds__(128, 3) pass1_kernel() {
    __shared__ float zf_dup[NKF][128];   // 32 KB
    __shared__ float e_s[32][128];       // 16 KB

    int tid = threadIdx.x;
    int tm8 = (tid >> 4) * 8;
    int tn = tid & 15;
    int row0 = (blockIdx.x & 255) * 64;
    int jsplit = blockIdx.x >> 8;
    int jbase = jsplit * JCHUNK;

    // stage duplicated zf tile
#pragma unroll
    for (int it = 0; it < 8; it++) {
        int f4 = it * 128 + tid;
        int kf = f4 >> 4, m4 = f4 & 15;
        float4 v = *reinterpret_cast<const float4*>(&g_zf2T[kf * NB + row0 + m4 * 4]);
        *reinterpret_cast<float4*>(&zf_dup[kf][m4 * 8]) =
            make_float4(v.x, v.x, v.y, v.y);
        *reinterpret_cast<float4*>(&zf_dup[kf][m4 * 8 + 4]) =
            make_float4(v.z, v.z, v.w, v.w);
    }
    float zn[8];
#pragma unroll
    for (int r = 0; r < 8; r++) zn[r] = g_znorm[row0 + tm8 + r];

    ull k1[8];
    unsigned v2[8];
#pragma unroll
    for (int r = 0; r < 8; r++) { k1[r] = ~0ULL; v2[r] = 0xFFFFFFFFu; }

    uint32_t sa = smem_u32(zf_dup) + tm8 * 8;
    uint32_t sb = smem_u32(e_s) + tn * 16;    // lane stride 16B: conflict-free

    for (int t = 0; t < JCHUNK / 128; t++) {
        int j0 = jbase + t * 128;
        ull acc[8][4];
#pragma unroll
        for (int r = 0; r < 8; r++)
#pragma unroll
            for (int c = 0; c < 4; c++) acc[r][c] = 0ULL;

#pragma unroll
        for (int ks = 0; ks < 2; ks++) {
            __syncthreads();
#pragma unroll
            for (int it = 0; it < 8; it++) {
                int f4 = it * 128 + tid;
                int kk = f4 >> 5, n4 = f4 & 31;
                *reinterpret_cast<float4*>(&e_s[kk][n4 * 4]) =
                    *reinterpret_cast<const float4*>(
                        &g_ef2T[(size_t)(ks * 32 + kk) * NJ + j0 + n4 * 4]);
            }
            __syncthreads();

            uint32_t sa_ks = sa + ks * 32 * 512;
#pragma unroll
            for (int kk = 0; kk < 32; kk++) {
                ull a0, a1, a2, a3, a4, a5, a6, a7, b0, b1, b2, b3;
                lds_v2u64(a0, a1, sa_ks + kk * 512);
                lds_v2u64(a2, a3, sa_ks + kk * 512 + 16);
                lds_v2u64(a4, a5, sa_ks + kk * 512 + 32);
                lds_v2u64(a6, a7, sa_ks + kk * 512 + 48);
                lds_v2u64(b0, b1, sb + kk * 512);          // j: tn*4 + {0..3}
                lds_v2u64(b2, b3, sb + kk * 512 + 256);    // j: 64+tn*4 + {0..3}
                ull av[8] = {a0, a1, a2, a3, a4, a5, a6, a7};
                ull bv[4] = {b0, b1, b2, b3};
#pragma unroll
                for (int r = 0; r < 8; r++)
#pragma unroll
                    for (int cc = 0; cc < 4; cc++)
                        ffma2(acc[r][cc], av[r], bv[cc]);
            }
        }

        // epilogue: pair c -> j = j0 + (c>>1)*64 + tn*4 + (c&1)*2 + {0,1}
        int jt = j0 + tn * 4;
#pragma unroll
        for (int cp = 0; cp < 4; cp++) {
            int jp = jt + (cp >> 1) * 64 + (cp & 1) * 2;
#pragma unroll
            for (int r = 0; r < 8; r++) {
                float lo, hi;
                unpack2(lo, hi, acc[r][cp]);
                unsigned u0 = __float_as_uint(zn[r] - lo);
                if (u0 < v2[r]) {
                    ull key = ((ull)u0 << 32) | (unsigned)jp;
                    if (key < k1[r]) { v2[r] = (unsigned)(k1[r] >> 32); k1[r] = key; }
                    else v2[r] = u0;
                }
                unsigned u1 = __float_as_uint(zn[r] - hi);
                if (u1 < v2[r]) {
                    ull key = ((ull)u1 << 32) | (unsigned)(jp + 1);
                    if (key < k1[r]) { v2[r] = (unsigned)(k1[r] >> 32); k1[r] = key; }
                    else v2[r] = u1;
                }
            }
        }
    }

    // block merge: per row, top-2 keys over the 16 thread-k1s, plus
    // v3 = min(3rd-smallest thread-k1 value, min thread-v2).
    __syncthreads();
    char* mbuf = reinterpret_cast<char*>(&e_s[0][0]);
    ull* K1 = reinterpret_cast<ull*>(mbuf);                     // [64][16] 8KB
    unsigned* V2 = reinterpret_cast<unsigned*>(mbuf + 8192);    // [64][16] 4KB
#pragma unroll
    for (int r = 0; r < 8; r++) {
        K1[(tm8 + r) * 16 + tn] = k1[r];
        V2[(tm8 + r) * 16 + tn] = v2[r];
    }
    __syncthreads();
    if (tid < 64) {
        ull bk1 = ~0ULL, bk2 = ~0ULL;
        unsigned bv3 = 0xFFFFFFFFu;
        for (int q = 0; q < 16; q++) {
            ull K = K1[tid * 16 + q];
            if (K < bk1) {
                unsigned s = (unsigned)(bk2 >> 32);
                if (s < bv3) bv3 = s;
                bk2 = bk1; bk1 = K;
            } else if (K < bk2) {
                unsigned s = (unsigned)(bk2 >> 32);
                if (s < bv3) bv3 = s;
                bk2 = K;
            } else {
                unsigned s = (unsigned)(K >> 32);
                if (s < bv3) bv3 = s;
            }
            unsigned v = V2[tid * 16 + q];
            if (v < bv3) bv3 = v;
        }
        int o = (row0 + tid) * JSPLIT + jsplit;
        g_k1[o] = bk1;
        g_k2[o] = bk2;
        g_v3[o] = bv3;
    }
}

// ---------------------------------------------------------------------------
// Merge per row: window over split bests; candidates = k1/k2 keys in window,
// exact fp32-chain re-rank; flag row for fallback only if a guard v3 enters
// the window (expected ~never).
// ---------------------------------------------------------------------------
__global__ void merge_exact_kernel(const float* __restrict__ e) {
    int b = blockIdx.x * 256 + threadIdx.x;
    float zn = g_znorm[b];
    float ulp = ldexpf(1.0f, ilogbf(fmaxf(zn, 1e-30f)) - 23);
    float W = 2.0f * ulp + 1e-6f;

    unsigned mu = 0xFFFFFFFFu;
#pragma unroll
    for (int s = 0; s < JSPLIT; s++) {
        unsigned sc = (unsigned)(g_k1[b * JSPLIT + s] >> 32);
        if (sc < mu) mu = sc;
    }
    float thr = __uint_as_float(mu) + W;
    unsigned thr_u = __float_as_uint(thr);

    int cj[2 * JSPLIT];
    int nc = 0;
    bool flag = false;
#pragma unroll
    for (int s = 0; s < JSPLIT; s++) {
        ull K1v = g_k1[b * JSPLIT + s];
        ull K2v = g_k2[b * JSPLIT + s];
        if ((unsigned)(K1v >> 32) <= thr_u) cj[nc++] = (int)(unsigned)K1v;
        if ((unsigned)(K2v >> 32) <= thr_u) cj[nc++] = (int)(unsigned)K2v;
        if (g_v3[b * JSPLIT + s] <= thr_u) flag = true;
    }
    if (flag) {
        int p = atomicAdd(&g_fbn, 1);
        g_fb[p] = b;
        return;
    }
    // exact chain (bitwise reference order) on candidates
    float zfr[NKF];
    const float4* zr4 = reinterpret_cast<const float4*>(&g_zf2R[b * NKF]);
#pragma unroll
    for (int i = 0; i < 16; i++) {
        float4 v = zr4[i];
        zfr[i * 4] = v.x; zfr[i * 4 + 1] = v.y;
        zfr[i * 4 + 2] = v.z; zfr[i * 4 + 3] = v.w;
    }
    float bestd = FLT_MAX;
    int bestj = 0x7FFFFFFF;
    for (int i = 0; i < nc; i++) {
        int j = cj[i];
        const float* er = e + (size_t)j * NDIM;
        float acc = 0.f;
#pragma unroll
        for (int k = 0; k < NDIM; k++)
            acc = fmaf(zfr[kf_of_k(k)], er[k], acc);
        float d = zn - acc;
        if (d < bestd || (d == bestd && j < bestj)) { bestd = d; bestj = j; }
    }
    g_idx[b] = bestj;
}

// ---------------------------------------------------------------------------
// Fallback: full exact scan for flagged rows (expected none).
// ---------------------------------------------------------------------------
__global__ void fallback_kernel(const float* __restrict__ e) {
    __shared__ float zfs[NKF];
    __shared__ ull slot;
    int n = g_fbn;
    for (int fi = blockIdx.x; fi < n; fi += gridDim.x) {
        int b = g_fb[fi];
        if (threadIdx.x < NKF) zfs[threadIdx.x] = g_zf2R[b * NKF + threadIdx.x];
        if (threadIdx.x == 0) slot = ~0ULL;
        __syncthreads();
        float zn = g_znorm[b];
        ull lb = ~0ULL;
        for (int j = threadIdx.x; j < NJ; j += 256) {
            const float* er = e + (size_t)j * NDIM;
            float acc = 0.f;
#pragma unroll
            for (int k = 0; k < NDIM; k++)
                acc = fmaf(zfs[kf_of_k(k)], er[k], acc);
            float d = zn - acc;
            ull key = ((ull)__float_as_uint(d) << 32) | (unsigned)j;
            if (key < lb) lb = key;
        }
        atomicMin(&slot, lb);
        __syncthreads();
        if (threadIdx.x == 0) g_idx[b] = (int)(slot & 0xFFFFFFFFu);
        __syncthreads();
    }
}

// ---------------------------------------------------------------------------
__global__ void gather_stats_kernel(const float* __restrict__ z,
                                    const float* __restrict__ e,
                                    float* __restrict__ outF, int out_size) {
    int t = blockIdx.x * 256 + threadIdx.x;
    int g0 = t * 4;
    int b = g0 >> 7;
    int i0 = g0 & 127;
    int j = g_idx[b];
    float4 zv = *reinterpret_cast<const float4*>(z + g0);
    float4 qv = *reinterpret_cast<const float4*>(e + (size_t)j * NDIM + i0);

    float q[4] = {qv.x, qv.y, qv.z, qv.w};
    float zz[4] = {zv.x, zv.y, zv.z, zv.w};
    float d[4], o[4];
#pragma unroll
    for (int u = 0; u < 4; u++) {
        d[u] = __fsub_rn(q[u], zz[u]);
        o[u] = __fadd_rn(zz[u], d[u]);
    }
    int c = i0 >> 3, h = (i0 >> 2) & 1;
    int ob = b * 128 + c * 2 + h;
    outF[ob]      = o[0];
    outF[ob + 32] = o[1];
    outF[ob + 64] = o[2];
    outF[ob + 96] = o[3];
    if (i0 == 0 && out_size >= N_ELEM + 1 + NB)
        outF[N_ELEM + 1 + b] = (float)j;

    float sd2 = 0.f, s1 = 0.f, s2 = 0.f, sxx = 0.f, syy = 0.f, sxy = 0.f;
#pragma unroll
    for (int u = 0; u < 4; u++) {
        sd2 = fmaf(d[u], d[u], sd2);
        s1 += q[u];
        s2 += zz[u];
        sxx = fmaf(q[u], q[u], sxx);
        syy = fmaf(zz[u], zz[u], syy);
        sxy = fmaf(q[u], zz[u], sxy);
    }
#pragma unroll
    for (int off = 16; off; off >>= 1) {
        sd2 += __shfl_down_sync(0xFFFFFFFFu, sd2, off);
        s1  += __shfl_down_sync(0xFFFFFFFFu, s1, off);
        s2  += __shfl_down_sync(0xFFFFFFFFu, s2, off);
        sxx += __shfl_down_sync(0xFFFFFFFFu, sxx, off);
        syy += __shfl_down_sync(0xFFFFFFFFu, syy, off);
        sxy += __shfl_down_sync(0xFFFFFFFFu, sxy, off);
    }
    __shared__ float sm[8][6];
    int wid = threadIdx.x >> 5, lane = threadIdx.x & 31;
    if (lane == 0) {
        sm[wid][0] = sd2; sm[wid][1] = s1; sm[wid][2] = s2;
        sm[wid][3] = sxx; sm[wid][4] = syy; sm[wid][5] = sxy;
    }
    __syncthreads();
    if (threadIdx.x < 6) {
        float a = 0.f;
#pragma unroll
        for (int w = 0; w < 8; w++) a += sm[w][threadIdx.x];
        g_partials[blockIdx.x * 6 + threadIdx.x] = a;
    }
}

// ---------------------------------------------------------------------------
__global__ void final_reduce_kernel(float* __restrict__ outF, int out_size) {
    __shared__ double smr[256];
    __shared__ double tot[6];
    double acc[6] = {0, 0, 0, 0, 0, 0};
    for (int p = threadIdx.x; p < N_STAT_BLOCKS; p += 256) {
#pragma unroll
        for (int s = 0; s < 6; s++) acc[s] += (double)g_partials[p * 6 + s];
    }
    for (int s = 0; s < 6; s++) {
        smr[threadIdx.x] = acc[s];
        __syncthreads();
        for (int off = 128; off > 0; off >>= 1) {
            if (threadIdx.x < off) smr[threadIdx.x] += smr[threadIdx.x + off];
            __syncthreads();
        }
        if (threadIdx.x == 0) tot[s] = smr[0];
        __syncthreads();
    }
    if (threadIdx.x == 0 && out_size >= N_ELEM + 1) {
        double N = (double)N_ELEM;
        double commit = 1.25 * tot[0] / N;
        double cov = tot[5] - tot[1] * tot[2] / N;
        double vx = tot[3] - tot[1] * tot[1] / N;
        double vy = tot[4] - tot[2] * tot[2] / N;
        double pearson = 0.5 + 0.5 * cov / (sqrt(vx) * sqrt(vy));
        double loss = commit + pearson + 0.01 * (double)g_colmax;
        outF[N_ELEM] = (float)loss;
    }
}

// ---------------------------------------------------------------------------
extern "C" void kernel_launch(void* const* d_in, const int* in_sizes, int n_in,
                              void* d_out, int out_size) {
    const float* z = (const float*)d_in[0];
    const float* e = (const float*)d_in[1];
    float* out = (float*)d_out;

    prep_z_kernel<<<NB / 128, 128>>>(z);
    fold_e_kernel<<<NJ / 128, 128>>>(e);
    colmax1_kernel<<<128, 128>>>(e);
    colmax2_kernel<<<1, 128>>>();
    pass1_kernel<<<256 * JSPLIT, 128>>>();
    merge_exact_kernel<<<NB / 256, 256>>>(e);
    fallback_kernel<<<32, 256>>>(e);
    gather_stats_kernel<<<N_ELEM / 1024, 256>>>(z, e, out, out_size);
    final_reduce_kernel<<<1, 256>>>(out, out_size);
}

// round 7
// speedup vs baseline: 3.3696x; 1.0396x over previous
#include <cuda_runtime.h>
#include <cstdint>
#include <float.h>
#include <math.h>

#define NB 16384
#define NJ 16384
#define NKF 64
#define NDIM 128
#define N_ELEM (NB * NDIM)
#define N_STAT_BLOCKS 2048
#define JSPLIT 16
#define JCHUNK (NJ / JSPLIT)

typedef unsigned long long ull;

// Scratch (device globals; no allocation allowed)
__device__ float g_zf2T[NKF * NB];     // 2*zf folded, [kf][b]
__device__ float g_zf2R[NB * NKF];     // 2*zf folded, row-major [b][kf]
__device__ float g_znorm[NB];
__device__ float g_ef2T[NKF * NJ];     // folded e sums, [kf][j]
__device__ ull   g_k1[NB * JSPLIT];    // per (row, split) best key (score|j)
__device__ ull   g_k2[NB * JSPLIT];    // per (row, split) 2nd key (score|j)
__device__ unsigned g_v3[NB * JSPLIT]; // guard value (3rd-smallest bound)
__device__ int   g_idx[NB];
__device__ int   g_fbn;
__device__ int   g_fb[NB];
__device__ float g_partials[N_STAT_BLOCKS * 6];
__device__ float g_colpart[128 * 128];
__device__ float g_colmax;

// ---------------------------------------------------------------------------
__device__ __forceinline__ uint32_t smem_u32(const void* p) {
    uint32_t r;
    asm("{ .reg .u64 t; cvta.to.shared.u64 t, %1; cvt.u32.u64 %0, t; }"
        : "=r"(r) : "l"(p));
    return r;
}
__device__ __forceinline__ void lds_v2u64(ull& x, ull& y, uint32_t addr) {
    asm volatile("ld.shared.v2.u64 {%0,%1}, [%2];" : "=l"(x), "=l"(y) : "r"(addr));
}
__device__ __forceinline__ void ffma2(ull& d, ull a, ull b) {
    asm("fma.rn.f32x2 %0, %1, %2, %0;" : "+l"(d) : "l"(a), "l"(b));
}
__device__ __forceinline__ void unpack2(float& lo, float& hi, ull v) {
    asm("mov.b64 {%0,%1}, %2;" : "=f"(lo), "=f"(hi) : "l"(v));
}

// Exact-chain fold map: kf(k) = (k>>6)*32 + (((k>>3)&7)<<2) + (k&3)
__device__ __forceinline__ int kf_of_k(int k) {
    return ((k >> 6) << 5) + (((k >> 3) & 7) << 2) + (k & 3);
}

// ---------------------------------------------------------------------------
__global__ void prep_z_kernel(const float* __restrict__ z) {
    int b = blockIdx.x * 128 + threadIdx.x;
    if (b == 0) g_fbn = 0;
    const float* zr = z + (size_t)b * NDIM;
    float sum = 0.f;
#pragma unroll
    for (int kf = 0; kf < NKF; kf++) {
        int c = kf >> 2, h = (kf >> 1) & 1, wp = kf & 1;
        int base = c * 8 + h * 4 + wp * 2;
        float2 p = *reinterpret_cast<const float2*>(zr + base);
        float v = p.x + p.y;
        g_zf2T[kf * NB + b] = v;
        g_zf2R[b * NKF + kf] = v;
        sum = fmaf(v, v, sum);
    }
    g_znorm[b] = 0.5f * sum;
}

// ---------------------------------------------------------------------------
__global__ void fold_e_kernel(const float* __restrict__ e) {
    int j = blockIdx.x * 128 + threadIdx.x;
    const float* er = e + (size_t)j * NDIM;
#pragma unroll
    for (int kf = 0; kf < NKF; kf++) {
        int ks = kf >> 5, q = kf & 31, g = q >> 2, r = q & 3;
        int ka = ks * 64 + g * 8 + r;
        g_ef2T[kf * NJ + j] = er[ka] + er[ka + 4];
    }
}

// ---------------------------------------------------------------------------
__global__ void colmax1_kernel(const float* __restrict__ e) {
    int t = threadIdx.x;
    int r0 = blockIdx.x * 128;
    float s = 0.f;
    for (int r = 0; r < 128; r++)
        s += fabsf(e[(size_t)(r0 + r) * NDIM + t]);
    g_colpart[blockIdx.x * 128 + t] = s;
}
__global__ void colmax2_kernel() {
    __shared__ float sm[128];
    int t = threadIdx.x;
    float s = 0.f;
    for (int bi = 0; bi < 128; bi++) s += g_colpart[bi * 128 + t];
    sm[t] = s;
    __syncthreads();
    for (int off = 64; off > 0; off >>= 1) {
        if (t < off) sm[t] = fmaxf(sm[t], sm[t + off]);
        __syncthreads();
    }
    if (t == 0) g_colmax = sm[0];
}

// ---------------------------------------------------------------------------
// Pass 1: folded K=64 FFMA2 GEMM, conflict-free LDS, branch-free min/max
// epilogue (best, bidx, v2-value per row; 6 instr/value, no BSSY).
// Block merge builds per (row, split): top-2 keys + guard value v3.
// ---------------------------------------------------------------------------
__global__ void __launch_bounds__(128, 3) pass1_kernel() {
    __shared__ float zf_dup[NKF][128];   // 32 KB
    __shared__ float e_s[32][128];       // 16 KB

    int tid = threadIdx.x;
    int tm8 = (tid >> 4) * 8;
    int tn = tid & 15;
    int row0 = (blockIdx.x & 255) * 64;
    int jsplit = blockIdx.x >> 8;
    int jbase = jsplit * JCHUNK;

    // stage duplicated zf tile
#pragma unroll
    for (int it = 0; it < 8; it++) {
        int f4 = it * 128 + tid;
        int kf = f4 >> 4, m4 = f4 & 15;
        float4 v = *reinterpret_cast<const float4*>(&g_zf2T[kf * NB + row0 + m4 * 4]);
        *reinterpret_cast<float4*>(&zf_dup[kf][m4 * 8]) =
            make_float4(v.x, v.x, v.y, v.y);
        *reinterpret_cast<float4*>(&zf_dup[kf][m4 * 8 + 4]) =
            make_float4(v.z, v.z, v.w, v.w);
    }
    float zn[8];
#pragma unroll
    for (int r = 0; r < 8; r++) zn[r] = g_znorm[row0 + tm8 + r];

    float best[8], v2[8];
    int bidx[8];
#pragma unroll
    for (int r = 0; r < 8; r++) { best[r] = FLT_MAX; v2[r] = FLT_MAX; bidx[r] = 0; }

    uint32_t sa = smem_u32(zf_dup) + tm8 * 8;
    uint32_t sb = smem_u32(e_s) + tn * 16;    // 16B lane stride: conflict-free

    for (int t = 0; t < JCHUNK / 128; t++) {
        int j0 = jbase + t * 128;
        ull acc[8][4];
#pragma unroll
        for (int r = 0; r < 8; r++)
#pragma unroll
            for (int c = 0; c < 4; c++) acc[r][c] = 0ULL;

#pragma unroll
        for (int ks = 0; ks < 2; ks++) {
            __syncthreads();
#pragma unroll
            for (int it = 0; it < 8; it++) {
                int f4 = it * 128 + tid;
                int kk = f4 >> 5, n4 = f4 & 31;
                *reinterpret_cast<float4*>(&e_s[kk][n4 * 4]) =
                    *reinterpret_cast<const float4*>(
                        &g_ef2T[(size_t)(ks * 32 + kk) * NJ + j0 + n4 * 4]);
            }
            __syncthreads();

            uint32_t sa_ks = sa + ks * 32 * 512;
#pragma unroll
            for (int kk = 0; kk < 32; kk++) {
                ull a0, a1, a2, a3, a4, a5, a6, a7, b0, b1, b2, b3;
                lds_v2u64(a0, a1, sa_ks + kk * 512);
                lds_v2u64(a2, a3, sa_ks + kk * 512 + 16);
                lds_v2u64(a4, a5, sa_ks + kk * 512 + 32);
                lds_v2u64(a6, a7, sa_ks + kk * 512 + 48);
                lds_v2u64(b0, b1, sb + kk * 512);          // j: tn*4 + {0..3}
                lds_v2u64(b2, b3, sb + kk * 512 + 256);    // j: 64+tn*4 + {0..3}
                ull av[8] = {a0, a1, a2, a3, a4, a5, a6, a7};
                ull bv[4] = {b0, b1, b2, b3};
#pragma unroll
                for (int r = 0; r < 8; r++)
#pragma unroll
                    for (int cc = 0; cc < 4; cc++)
                        ffma2(acc[r][cc], av[r], bv[cc]);
            }
        }

        // branch-free epilogue: pair cp -> j = j0 + (cp>>1)*64 + tn*4 + (cp&1)*2
        int jt = j0 + tn * 4;
#pragma unroll
        for (int cp = 0; cp < 4; cp++) {
            int jp = jt + (cp >> 1) * 64 + (cp & 1) * 2;
#pragma unroll
            for (int r = 0; r < 8; r++) {
                float lo, hi;
                unpack2(lo, hi, acc[r][cp]);
                float s0 = zn[r] - lo;
                v2[r] = fminf(v2[r], fmaxf(s0, best[r]));
                if (s0 < best[r]) bidx[r] = jp;
                best[r] = fminf(s0, best[r]);
                float s1 = zn[r] - hi;
                v2[r] = fminf(v2[r], fmaxf(s1, best[r]));
                if (s1 < best[r]) bidx[r] = jp + 1;
                best[r] = fminf(s1, best[r]);
            }
        }
    }

    // block merge (cold): per row, top-2 keys over 16 thread-bests +
    // v3 = min(3rd-smallest thread-best, min thread-v2). Keys packed here.
    __syncthreads();
    char* mbuf = reinterpret_cast<char*>(&e_s[0][0]);
    float* BV = reinterpret_cast<float*>(mbuf);                 // [64][16] 4KB
    int* BJ = reinterpret_cast<int*>(mbuf + 4096);              // [64][16] 4KB
    float* V2 = reinterpret_cast<float*>(mbuf + 8192);          // [64][16] 4KB
#pragma unroll
    for (int r = 0; r < 8; r++) {
        BV[(tm8 + r) * 16 + tn] = best[r];
        BJ[(tm8 + r) * 16 + tn] = bidx[r];
        V2[(tm8 + r) * 16 + tn] = v2[r];
    }
    __syncthreads();
    if (tid < 64) {
        ull bk1 = ~0ULL, bk2 = ~0ULL;
        unsigned bv3 = 0xFFFFFFFFu;
        for (int q = 0; q < 16; q++) {
            unsigned sb_ = __float_as_uint(BV[tid * 16 + q]);
            ull K = ((ull)sb_ << 32) | (unsigned)BJ[tid * 16 + q];
            if (K < bk1) {
                unsigned s = (unsigned)(bk2 >> 32);
                if (s < bv3) bv3 = s;
                bk2 = bk1; bk1 = K;
            } else if (K < bk2) {
                unsigned s = (unsigned)(bk2 >> 32);
                if (s < bv3) bv3 = s;
                bk2 = K;
            } else {
                if (sb_ < bv3) bv3 = sb_;
            }
            unsigned v = __float_as_uint(V2[tid * 16 + q]);
            if (v < bv3) bv3 = v;
        }
        int o = (row0 + tid) * JSPLIT + jsplit;
        g_k1[o] = bk1;
        g_k2[o] = bk2;
        g_v3[o] = bv3;
    }
}

// ---------------------------------------------------------------------------
// Merge per row: window over split bests; candidates = k1/k2 keys in window,
// exact fp32-chain re-rank; flag for fallback only if a guard v3 enters.
// ---------------------------------------------------------------------------
__global__ void merge_exact_kernel(const float* __restrict__ e) {
    int b = blockIdx.x * 256 + threadIdx.x;
    float zn = g_znorm[b];
    float ulp = ldexpf(1.0f, ilogbf(fmaxf(zn, 1e-30f)) - 23);
    float W = 2.0f * ulp + 1e-6f;

    unsigned mu = 0xFFFFFFFFu;
#pragma unroll
    for (int s = 0; s < JSPLIT; s++) {
        unsigned sc = (unsigned)(g_k1[b * JSPLIT + s] >> 32);
        if (sc < mu) mu = sc;
    }
    float thr = __uint_as_float(mu) + W;
    unsigned thr_u = __float_as_uint(thr);

    int cj[2 * JSPLIT];
    int nc = 0;
    bool flag = false;
#pragma unroll
    for (int s = 0; s < JSPLIT; s++) {
        ull K1v = g_k1[b * JSPLIT + s];
        ull K2v = g_k2[b * JSPLIT + s];
        if ((unsigned)(K1v >> 32) <= thr_u) cj[nc++] = (int)(unsigned)K1v;
        if ((unsigned)(K2v >> 32) <= thr_u) cj[nc++] = (int)(unsigned)K2v;
        if (g_v3[b * JSPLIT + s] <= thr_u) flag = true;
    }
    if (flag) {
        int p = atomicAdd(&g_fbn, 1);
        g_fb[p] = b;
        return;
    }
    // exact chain (bitwise reference order) on candidates
    float zfr[NKF];
    const float4* zr4 = reinterpret_cast<const float4*>(&g_zf2R[b * NKF]);
#pragma unroll
    for (int i = 0; i < 16; i++) {
        float4 v = zr4[i];
        zfr[i * 4] = v.x; zfr[i * 4 + 1] = v.y;
        zfr[i * 4 + 2] = v.z; zfr[i * 4 + 3] = v.w;
    }
    float bestd = FLT_MAX;
    int bestj = 0x7FFFFFFF;
    for (int i = 0; i < nc; i++) {
        int j = cj[i];
        const float* er = e + (size_t)j * NDIM;
        float acc = 0.f;
#pragma unroll
        for (int k = 0; k < NDIM; k++)
            acc = fmaf(zfr[kf_of_k(k)], er[k], acc);
        float d = zn - acc;
        if (d < bestd || (d == bestd && j < bestj)) { bestd = d; bestj = j; }
    }
    g_idx[b] = bestj;
}

// ---------------------------------------------------------------------------
__global__ void fallback_kernel(const float* __restrict__ e) {
    __shared__ float zfs[NKF];
    __shared__ ull slot;
    int n = g_fbn;
    for (int fi = blockIdx.x; fi < n; fi += gridDim.x) {
        int b = g_fb[fi];
        if (threadIdx.x < NKF) zfs[threadIdx.x] = g_zf2R[b * NKF + threadIdx.x];
        if (threadIdx.x == 0) slot = ~0ULL;
        __syncthreads();
        float zn = g_znorm[b];
        ull lb = ~0ULL;
        for (int j = threadIdx.x; j < NJ; j += 256) {
            const float* er = e + (size_t)j * NDIM;
            float acc = 0.f;
#pragma unroll
            for (int k = 0; k < NDIM; k++)
                acc = fmaf(zfs[kf_of_k(k)], er[k], acc);
            float d = zn - acc;
            ull key = ((ull)__float_as_uint(d) << 32) | (unsigned)j;
            if (key < lb) lb = key;
        }
        atomicMin(&slot, lb);
        __syncthreads();
        if (threadIdx.x == 0) g_idx[b] = (int)(slot & 0xFFFFFFFFu);
        __syncthreads();
    }
}

// ---------------------------------------------------------------------------
__global__ void gather_stats_kernel(const float* __restrict__ z,
                                    const float* __restrict__ e,
                                    float* __restrict__ outF, int out_size) {
    int t = blockIdx.x * 256 + threadIdx.x;
    int g0 = t * 4;
    int b = g0 >> 7;
    int i0 = g0 & 127;
    int j = g_idx[b];
    float4 zv = *reinterpret_cast<const float4*>(z + g0);
    float4 qv = *reinterpret_cast<const float4*>(e + (size_t)j * NDIM + i0);

    float q[4] = {qv.x, qv.y, qv.z, qv.w};
    float zz[4] = {zv.x, zv.y, zv.z, zv.w};
    float d[4], o[4];
#pragma unroll
    for (int u = 0; u < 4; u++) {
        d[u] = __fsub_rn(q[u], zz[u]);
        o[u] = __fadd_rn(zz[u], d[u]);
    }
    int c = i0 >> 3, h = (i0 >> 2) & 1;
    int ob = b * 128 + c * 2 + h;
    outF[ob]      = o[0];
    outF[ob + 32] = o[1];
    outF[ob + 64] = o[2];
    outF[ob + 96] = o[3];
    if (i0 == 0 && out_size >= N_ELEM + 1 + NB)
        outF[N_ELEM + 1 + b] = (float)j;

    float sd2 = 0.f, s1 = 0.f, s2 = 0.f, sxx = 0.f, syy = 0.f, sxy = 0.f;
#pragma unroll
    for (int u = 0; u < 4; u++) {
        sd2 = fmaf(d[u], d[u], sd2);
        s1 += q[u];
        s2 += zz[u];
        sxx = fmaf(q[u], q[u], sxx);
        syy = fmaf(zz[u], zz[u], syy);
        sxy = fmaf(q[u], zz[u], sxy);
    }
#pragma unroll
    for (int off = 16; off; off >>= 1) {
        sd2 += __shfl_down_sync(0xFFFFFFFFu, sd2, off);
        s1  += __shfl_down_sync(0xFFFFFFFFu, s1, off);
        s2  += __shfl_down_sync(0xFFFFFFFFu, s2, off);
        sxx += __shfl_down_sync(0xFFFFFFFFu, sxx, off);
        syy += __shfl_down_sync(0xFFFFFFFFu, syy, off);
        sxy += __shfl_down_sync(0xFFFFFFFFu, sxy, off);
    }
    __shared__ float sm[8][6];
    int wid = threadIdx.x >> 5, lane = threadIdx.x & 31;
    if (lane == 0) {
        sm[wid][0] = sd2; sm[wid][1] = s1; sm[wid][2] = s2;
        sm[wid][3] = sxx; sm[wid][4] = syy; sm[wid][5] = sxy;
    }
    __syncthreads();
    if (threadIdx.x < 6) {
        float a = 0.f;
#pragma unroll
        for (int w = 0; w < 8; w++) a += sm[w][threadIdx.x];
        g_partials[blockIdx.x * 6 + threadIdx.x] = a;
    }
}

// ---------------------------------------------------------------------------
__global__ void final_reduce_kernel(float* __restrict__ outF, int out_size) {
    __shared__ double smr[256];
    __shared__ double tot[6];
    double acc[6] = {0, 0, 0, 0, 0, 0};
    for (int p = threadIdx.x; p < N_STAT_BLOCKS; p += 256) {
#pragma unroll
        for (int s = 0; s < 6; s++) acc[s] += (double)g_partials[p * 6 + s];
    }
    for (int s = 0; s < 6; s++) {
        smr[threadIdx.x] = acc[s];
        __syncthreads();
        for (int off = 128; off > 0; off >>= 1) {
            if (threadIdx.x < off) smr[threadIdx.x] += smr[threadIdx.x + off];
            __syncthreads();
        }
        if (threadIdx.x == 0) tot[s] = smr[0];
        __syncthreads();
    }
    if (threadIdx.x == 0 && out_size >= N_ELEM + 1) {
        double N = (double)N_ELEM;
        double commit = 1.25 * tot[0] / N;
        double cov = tot[5] - tot[1] * tot[2] / N;
        double vx = tot[3] - tot[1] * tot[1] / N;
        double vy = tot[4] - tot[2] * tot[2] / N;
        double pearson = 0.5 + 0.5 * cov / (sqrt(vx) * sqrt(vy));
        double loss = commit + pearson + 0.01 * (double)g_colmax;
        outF[N_ELEM] = (float)loss;
    }
}

// ---------------------------------------------------------------------------
extern "C" void kernel_launch(void* const* d_in, const int* in_sizes, int n_in,
                              void* d_out, int out_size) {
    const float* z = (const float*)d_in[0];
    const float* e = (const float*)d_in[1];
    float* out = (float*)d_out;

    // pass1 placed 4th: that's the launch slot ncu captures (-s 5 -c 1).
    prep_z_kernel<<<NB / 128, 128>>>(z);
    fold_e_kernel<<<NJ / 128, 128>>>(e);
    colmax1_kernel<<<128, 128>>>(e);
    pass1_kernel<<<256 * JSPLIT, 128>>>();
    colmax2_kernel<<<1, 128>>>();
    merge_exact_kernel<<<NB / 256, 256>>>(e);
    fallback_kernel<<<32, 256>>>(e);
    gather_stats_kernel<<<N_ELEM / 1024, 256>>>(z, e, out, out_size);
    final_reduce_kernel<<<1, 256>>>(out, out_size);
}